// round 4
// baseline (speedup 1.0000x reference)
#include <cuda_runtime.h>
#include <cstdint>

#define MAX_E 100000
#define MAX_T 1000000
#define CCH   64
#define SCAN_BLK 512
#define MAX_SCAN_BLOCKS ((MAX_E + SCAN_BLK - 1) / SCAN_BLK)

#define CAP      224          // CSR slots per block window
#define MAXROW   320          // CAP + max segment length (96)
#define RS       65           // padded smem row stride (conflict-free)
#define SEOFF_MX 384
#define MAX_NB   (MAX_T / CAP + 3)

// dynamic smem layout: srows[MAXROW*RS] | sex[MAXROW] | seoff[SEOFF_MX]
#define SMEM_DYN ((MAXROW * RS + MAXROW + SEOFF_MX) * 4)

// Scratch (device globals — allocation-free per harness rules)
__device__ float4   g_rnorm4[MAX_E];
__device__ unsigned g_cnt[MAX_E];
__device__ unsigned g_off[MAX_E];
__device__ unsigned g_cursor[MAX_E];
__device__ unsigned g_bsum[MAX_SCAN_BLOCKS];
__device__ int      g_csrc[MAX_T];    // src ids, CSR(dst)-ordered
__device__ float    g_cth[MAX_T];     // clipped cos(theta), CSR-ordered
__device__ int      g_bstart[MAX_NB]; // first edge per slot-window

// ---------------------------------------------------------------------------
__global__ void k_prep(const float* __restrict__ r, int E) {
    int i = blockIdx.x * blockDim.x + threadIdx.x;
    if (i >= E) return;
    float x = r[3 * i + 0], y = r[3 * i + 1], z = r[3 * i + 2];
    float inv = rsqrtf(x * x + y * y + z * z);
    g_rnorm4[i] = make_float4(x * inv, y * inv, z * inv, 0.0f);
    g_cnt[i] = 0u;
    g_cursor[i] = 0u;
}

__global__ void k_count(const int* __restrict__ tdst, int T) {
    int t = blockIdx.x * blockDim.x + threadIdx.x;
    if (t < T) atomicAdd(&g_cnt[tdst[t]], 1u);
}

// --------------------------- exclusive scan --------------------------------
__global__ void k_scan1(int E) {
    __shared__ unsigned sh[SCAN_BLK];
    int i = blockIdx.x * SCAN_BLK + threadIdx.x;
    unsigned v = (i < E) ? g_cnt[i] : 0u;
    sh[threadIdx.x] = v;
    __syncthreads();
    unsigned incl = v;
    for (int ofs = 1; ofs < SCAN_BLK; ofs <<= 1) {
        unsigned add = (threadIdx.x >= ofs) ? sh[threadIdx.x - ofs] : 0u;
        __syncthreads();
        incl += add;
        sh[threadIdx.x] = incl;
        __syncthreads();
    }
    if (i < E) g_off[i] = incl - v;
    if (threadIdx.x == SCAN_BLK - 1) g_bsum[blockIdx.x] = incl;
}

__global__ void k_scan2(int nb) {
    __shared__ unsigned sh[SCAN_BLK];
    unsigned v = (threadIdx.x < nb) ? g_bsum[threadIdx.x] : 0u;
    sh[threadIdx.x] = v;
    __syncthreads();
    unsigned incl = v;
    for (int ofs = 1; ofs < SCAN_BLK; ofs <<= 1) {
        unsigned add = (threadIdx.x >= ofs) ? sh[threadIdx.x - ofs] : 0u;
        __syncthreads();
        incl += add;
        sh[threadIdx.x] = incl;
        __syncthreads();
    }
    if (threadIdx.x < nb) g_bsum[threadIdx.x] = incl - v;
}

__global__ void k_scan3(int E) {
    int i = blockIdx.x * SCAN_BLK + threadIdx.x;
    if (i < E) g_off[i] += g_bsum[blockIdx.x];
}

// ---------------------------------------------------------------------------
// bstart: g_bstart[b] = first edge with off >= b*CAP
// ---------------------------------------------------------------------------
__global__ void k_bstart(int E, int T, int nb) {
    int e = blockIdx.x * blockDim.x + threadIdx.x;
    if (e >= E) return;
    int be = (int)g_off[e] / CAP;
    int bp = (e == 0) ? -1 : (int)g_off[e - 1] / CAP;
    for (int b = bp + 1; b <= be; b++) g_bstart[b] = e;
    if (e == E - 1)
        for (int b = be + 1; b <= nb; b++) g_bstart[b] = E;
}

// ---------------------------------------------------------------------------
// perm: CSR scatter of src ids + precomputed clipped cos(theta)
// ---------------------------------------------------------------------------
__global__ void k_perm(const int* __restrict__ tsrc, const int* __restrict__ tdst, int T) {
    int t = blockIdx.x * blockDim.x + threadIdx.x;
    if (t >= T) return;
    int s = tsrc[t], d = tdst[t];
    unsigned pos = g_off[d] + atomicAdd(&g_cursor[d], 1u);
    float4 rs = __ldg(&g_rnorm4[s]);
    float4 rd = __ldg(&g_rnorm4[d]);
    float cth = rs.x * rd.x + rs.y * rd.y + rs.z * rd.z;
    cth = fminf(fmaxf(cth, -1.0f + 1e-6f), 1.0f - 1e-6f);
    g_csrc[pos] = s;
    g_cth[pos] = cth;
}

// ---------------------------------------------------------------------------
// fused: per-block tile of CSR slots.
//  stage src rows -> smem; logits+exp thread-per-slot; warp-per-edge aggregate.
//  softmax computed without max-subtraction (|logit| << 88, mathematically
//  identical alpha = exp(a)/sum exp(a)).
// ---------------------------------------------------------------------------
__global__ void __launch_bounds__(256)
k_fused(const float* __restrict__ xij, const float* __restrict__ attn,
        float* __restrict__ ft, int E, int T) {
    extern __shared__ float dsm[];
    float* srows = dsm;                       // MAXROW * RS
    float* sex   = srows + MAXROW * RS;       // MAXROW
    int*   seoff = (int*)(sex + MAXROW);      // SEOFF_MX
    __shared__ float sat[CCH];
    __shared__ int smeta[4];

    int tid = threadIdx.x, lane = tid & 31, w = tid >> 5;
    if (tid < CCH) sat[tid] = attn[tid];
    if (tid == 0) {
        int e_lo = g_bstart[blockIdx.x];
        int e_hi = g_bstart[blockIdx.x + 1];
        int e_cnt = e_hi - e_lo;
        if (e_cnt > SEOFF_MX - 1) e_cnt = SEOFF_MX - 1;
        int base = 0, n = 0;
        if (e_cnt > 0) {
            base = (int)g_off[e_lo];
            int end = (e_lo + e_cnt < E) ? (int)g_off[e_lo + e_cnt] : T;
            n = end - base;
            if (n > MAXROW) n = MAXROW;
        }
        smeta[0] = e_lo; smeta[1] = e_cnt; smeta[2] = base; smeta[3] = n;
    }
    __syncthreads();
    int e_lo = smeta[0], e_cnt = smeta[1], base = smeta[2], n = smeta[3];
    if (e_cnt <= 0) return;

    // local segment boundaries
    for (int i = tid; i <= e_cnt; i += blockDim.x) {
        int v = (i == e_cnt) ? n : (int)g_off[e_lo + i] - base;
        seoff[i] = (v > n) ? n : v;
    }

    // stage src rows (warp-cooperative, coalesced)
    for (int j = w; j < n; j += 256 / 32) {
        int s = __ldg(&g_csrc[base + j]);
        float2 v = __ldg((const float2*)(xij + (size_t)s * CCH) + lane);
        srows[j * RS + 2 * lane]     = v.x;
        srows[j * RS + 2 * lane + 1] = v.y;
    }
    __syncthreads();

    // phase B: logits + exp, thread-per-slot
    for (int j = tid; j < n; j += blockDim.x) {
        // last local edge with seoff[le] <= j
        int lo = 0, hi = e_cnt - 1;
        while (lo < hi) {
            int mid = (lo + hi + 1) >> 1;
            if (seoff[mid] <= j) lo = mid; else hi = mid - 1;
        }
        int d = e_lo + lo;

        float cth = __ldg(&g_cth[base + j]);
        float c2 = 2.0f * cth;
        float zp = cth, zc = 1.0f;        // T_{-1}, T_0

        const float4* xd = (const float4*)(xij + (size_t)d * CCH);
        const float* row = &srows[j * RS];
        float a = 0.0f;
#pragma unroll
        for (int k = 0; k < CCH / 4; k++) {
            float4 D = __ldg(xd + k);
            float dv[4] = {D.x, D.y, D.z, D.w};
#pragma unroll
            for (int q = 0; q < 4; q++) {
                int c = 4 * k + q;
                float v = zc + row[c] + dv[q];
                float e = __fdividef(v, 1.0f + __expf(-v));   // silu
                a = fmaf(e, sat[c], a);
                float zn = fmaf(c2, zc, -zp);                 // Chebyshev
                zp = zc; zc = zn;
            }
        }
        sex[j] = __expf(a);
    }
    __syncthreads();

    // phase C: warp-per-edge aggregate from smem
    for (int el = w; el < e_cnt; el += 256 / 32) {
        int lo = seoff[el], hi = seoff[el + 1];
        float acc0 = 0.0f, acc1 = 0.0f, den = 0.0f;
        for (int i = lo; i < hi; i++) {
            float e = sex[i];
            den += e;
            acc0 = fmaf(e, srows[i * RS + lane],      acc0);
            acc1 = fmaf(e, srows[i * RS + 32 + lane], acc1);
        }
        float inv = (hi > lo) ? __fdividef(1.0f, den) : 0.0f;
        size_t o = (size_t)(e_lo + el) * CCH;
        ft[o + lane]      = acc0 * inv;
        ft[o + 32 + lane] = acc1 * inv;
    }
}

// ---------------------------------------------------------------------------
extern "C" void kernel_launch(void* const* d_in, const int* in_sizes, int n_in,
                              void* d_out, int out_size) {
    const float* xij  = (const float*)d_in[0];
    const float* r    = (const float*)d_in[1];
    const float* attn = (const float*)d_in[2];
    const int*   tsrc = (const int*)d_in[3];
    const int*   tdst = (const int*)d_in[4];
    float* ft = (float*)d_out;

    int E = in_sizes[1] / 3;
    int T = in_sizes[3];
    int nsb = (E + SCAN_BLK - 1) / SCAN_BLK;
    int nb  = (T + CAP - 1) / CAP;

    cudaFuncSetAttribute(k_fused, cudaFuncAttributeMaxDynamicSharedMemorySize, SMEM_DYN);

    k_prep  <<<(E + 255) / 256, 256>>>(r, E);
    k_count <<<(T + 255) / 256, 256>>>(tdst, T);
    k_scan1 <<<nsb, SCAN_BLK>>>(E);
    k_scan2 <<<1,   SCAN_BLK>>>(nsb);
    k_scan3 <<<nsb, SCAN_BLK>>>(E);
    k_bstart<<<(E + 255) / 256, 256>>>(E, T, nb);
    k_perm  <<<(T + 255) / 256, 256>>>(tsrc, tdst, T);
    k_fused <<<nb, 256, SMEM_DYN>>>(xij, attn, ft, E, T);
}

// round 5
// speedup vs baseline: 1.4293x; 1.4293x over previous
#include <cuda_runtime.h>
#include <cstdint>

#define MAX_E 100000
#define MAX_T 1000000
#define CCH   64
#define SCAN_BLK 512
#define MAX_SCAN_BLOCKS ((MAX_E + SCAN_BLK - 1) / SCAN_BLK)
#define TPB1 128   // pass1: triplets per block

// Scratch (device globals — allocation-free per harness rules).
// g_cnt / g_cursor: zero at module load; k_edge re-zeroes them at the end of
// every run, so each kernel_launch invocation sees zeros on entry.
__device__ float4   g_rnorm4[MAX_E];
__device__ unsigned g_cnt[MAX_E];
__device__ unsigned g_off[MAX_E];
__device__ unsigned g_cursor[MAX_E];
__device__ unsigned g_bsum[MAX_SCAN_BLOCKS];
__device__ float    g_cex[MAX_T];    // exp(logit), CSR(dst)-ordered
__device__ int      g_csrc[MAX_T];   // src ids, CSR(dst)-ordered
__device__ int      g_cdst[MAX_T];   // dst ids, CSR(dst)-ordered

// ---------------------------------------------------------------------------
// prep+count fused: unit bond dirs for i<E; degree histogram for i<T
// ---------------------------------------------------------------------------
__global__ void k_prep_count(const float* __restrict__ r,
                             const int* __restrict__ tdst, int E, int T) {
    int i = blockIdx.x * blockDim.x + threadIdx.x;
    if (i < E) {
        float x = r[3 * i + 0], y = r[3 * i + 1], z = r[3 * i + 2];
        float inv = rsqrtf(x * x + y * y + z * z);
        g_rnorm4[i] = make_float4(x * inv, y * inv, z * inv, 0.0f);
    }
    if (i < T) atomicAdd(&g_cnt[tdst[i]], 1u);
}

// --------------------------- exclusive scan --------------------------------
__global__ void k_scan1(int E) {
    __shared__ unsigned sh[SCAN_BLK];
    int i = blockIdx.x * SCAN_BLK + threadIdx.x;
    unsigned v = (i < E) ? g_cnt[i] : 0u;
    sh[threadIdx.x] = v;
    __syncthreads();
    unsigned incl = v;
    for (int ofs = 1; ofs < SCAN_BLK; ofs <<= 1) {
        unsigned add = (threadIdx.x >= ofs) ? sh[threadIdx.x - ofs] : 0u;
        __syncthreads();
        incl += add;
        sh[threadIdx.x] = incl;
        __syncthreads();
    }
    if (i < E) g_off[i] = incl - v;
    if (threadIdx.x == SCAN_BLK - 1) g_bsum[blockIdx.x] = incl;
}

__global__ void k_scan2(int nb) {
    __shared__ unsigned sh[SCAN_BLK];
    unsigned v = (threadIdx.x < nb) ? g_bsum[threadIdx.x] : 0u;
    sh[threadIdx.x] = v;
    __syncthreads();
    unsigned incl = v;
    for (int ofs = 1; ofs < SCAN_BLK; ofs <<= 1) {
        unsigned add = (threadIdx.x >= ofs) ? sh[threadIdx.x - ofs] : 0u;
        __syncthreads();
        incl += add;
        sh[threadIdx.x] = incl;
        __syncthreads();
    }
    if (threadIdx.x < nb) g_bsum[threadIdx.x] = incl - v;
}

__global__ void k_scan3(int E) {
    int i = blockIdx.x * SCAN_BLK + threadIdx.x;
    if (i < E) g_off[i] += g_bsum[blockIdx.x];
}

// ---------------------------------------------------------------------------
// perm: scatter triplets into CSR(dst) order
// ---------------------------------------------------------------------------
__global__ void k_perm(const int* __restrict__ tsrc, const int* __restrict__ tdst, int T) {
    int t = blockIdx.x * blockDim.x + threadIdx.x;
    if (t >= T) return;
    int d = tdst[t];
    unsigned pos = g_off[d] + atomicAdd(&g_cursor[d], 1u);
    g_csrc[pos] = tsrc[t];
    g_cdst[pos] = d;
}

// ---------------------------------------------------------------------------
// pass1: exp(logit) in CSR order.
//  - xij[src] rows staged to smem (warp-cooperative coalesced; stride 65)
//  - xij[dst] direct: CSR adjacency -> few distinct rows/warp, L1-hits
//  - Chebyshev 3-term recurrence (1 FMA/channel)
//  - stores exp(a): softmax needs no max subtraction here (|a| << 88;
//    alpha = e^a / sum e^a identically — validated in R4, rel_err 6.6e-6)
// ---------------------------------------------------------------------------
__global__ void __launch_bounds__(TPB1)
k_pass1(const float* __restrict__ xij, const float* __restrict__ attn, int T) {
    __shared__ float sx[TPB1 * 65];
    __shared__ float sat[CCH];
    int tid = threadIdx.x;
    int base = blockIdx.x * TPB1;
    if (tid < CCH) sat[tid] = attn[tid];

    int lane = tid & 31, w = tid >> 5;
    for (int j = w; j < TPB1; j += TPB1 / 32) {
        int t = base + j;
        if (t < T) {
            int s = g_csrc[t];
            float2 v = __ldg((const float2*)(xij + (size_t)s * CCH) + lane);
            sx[j * 65 + 2 * lane]     = v.x;
            sx[j * 65 + 2 * lane + 1] = v.y;
        }
    }
    __syncthreads();

    int t = base + tid;
    if (t >= T) return;
    int s = g_csrc[t], d = g_cdst[t];

    float4 rs = __ldg(&g_rnorm4[s]);
    float4 rd = __ldg(&g_rnorm4[d]);
    float cth = rs.x * rd.x + rs.y * rd.y + rs.z * rd.z;
    cth = fminf(fmaxf(cth, -1.0f + 1e-6f), 1.0f - 1e-6f);
    float c2 = 2.0f * cth;
    float zp = cth, zc = 1.0f;   // T_{-1}, T_0

    const float4* xd = (const float4*)(xij + (size_t)d * CCH);
    const float* row = &sx[tid * 65];
    float a = 0.0f;

#pragma unroll
    for (int k = 0; k < CCH / 4; k++) {
        float4 D = __ldg(xd + k);
        float dv[4] = {D.x, D.y, D.z, D.w};
#pragma unroll
        for (int j = 0; j < 4; j++) {
            int c = 4 * k + j;
            float v = zc + row[c] + dv[j];
            float e = __fdividef(v, 1.0f + __expf(-v));   // silu
            a = fmaf(e, sat[c], a);
            float zn = fmaf(c2, zc, -zp);                 // Chebyshev step
            zp = zc; zc = zn;
        }
    }
    g_cex[t] = __expf(a);   // coalesced
}

// ---------------------------------------------------------------------------
// edge: warp-per-edge single-pass aggregate: ft = (sum ex*x[src]) / sum ex.
// Each lane owns channels {2*lane, 2*lane+1} (float2 loads/stores).
// Resets g_cnt / g_cursor for the next run (self-restoring global state).
// ---------------------------------------------------------------------------
__global__ void __launch_bounds__(256)
k_edge(const float* __restrict__ xij, float* __restrict__ ft, int E) {
    int warp = (blockIdx.x * blockDim.x + threadIdx.x) >> 5;
    int lane = threadIdx.x & 31;
    if (warp >= E) return;

    int base = (int)g_off[warp];
    int deg  = (int)g_cnt[warp];

    float ax = 0.0f, ay = 0.0f, den = 0.0f;

    int i = 0;
    for (; i + 4 <= deg; i += 4) {
        float e0 = g_cex[base + i + 0], e1 = g_cex[base + i + 1];
        float e2 = g_cex[base + i + 2], e3 = g_cex[base + i + 3];
        int s0 = g_csrc[base + i + 0], s1 = g_csrc[base + i + 1];
        int s2 = g_csrc[base + i + 2], s3 = g_csrc[base + i + 3];
        float2 v0 = __ldg((const float2*)(xij + (size_t)s0 * CCH) + lane);
        float2 v1 = __ldg((const float2*)(xij + (size_t)s1 * CCH) + lane);
        float2 v2 = __ldg((const float2*)(xij + (size_t)s2 * CCH) + lane);
        float2 v3 = __ldg((const float2*)(xij + (size_t)s3 * CCH) + lane);
        den += (e0 + e1) + (e2 + e3);
        ax = fmaf(e0, v0.x, ax); ay = fmaf(e0, v0.y, ay);
        ax = fmaf(e1, v1.x, ax); ay = fmaf(e1, v1.y, ay);
        ax = fmaf(e2, v2.x, ax); ay = fmaf(e2, v2.y, ay);
        ax = fmaf(e3, v3.x, ax); ay = fmaf(e3, v3.y, ay);
    }
    for (; i < deg; i++) {
        float e0 = g_cex[base + i];
        int s0 = g_csrc[base + i];
        float2 v0 = __ldg((const float2*)(xij + (size_t)s0 * CCH) + lane);
        den += e0;
        ax = fmaf(e0, v0.x, ax); ay = fmaf(e0, v0.y, ay);
    }

    float inv = (deg > 0) ? __fdividef(1.0f, den) : 0.0f;
    float2 out = make_float2(ax * inv, ay * inv);
    *((float2*)(ft + (size_t)warp * CCH) + lane) = out;

    if (lane == 0) {                // restore invariant for next run
        g_cnt[warp] = 0u;
        g_cursor[warp] = 0u;
    }
}

// ---------------------------------------------------------------------------
extern "C" void kernel_launch(void* const* d_in, const int* in_sizes, int n_in,
                              void* d_out, int out_size) {
    const float* xij  = (const float*)d_in[0];
    const float* r    = (const float*)d_in[1];
    const float* attn = (const float*)d_in[2];
    const int*   tsrc = (const int*)d_in[3];
    const int*   tdst = (const int*)d_in[4];
    float* ft = (float*)d_out;

    int E = in_sizes[1] / 3;
    int T = in_sizes[3];
    int nsb = (E + SCAN_BLK - 1) / SCAN_BLK;
    int nmx = (T > E) ? T : E;

    k_prep_count<<<(nmx + 255) / 256, 256>>>(r, tdst, E, T);
    k_scan1<<<nsb, SCAN_BLK>>>(E);
    k_scan2<<<1,   SCAN_BLK>>>(nsb);
    k_scan3<<<nsb, SCAN_BLK>>>(E);
    k_perm <<<(T + 255) / 256, 256>>>(tsrc, tdst, T);
    k_pass1<<<(T + TPB1 - 1) / TPB1, TPB1>>>(xij, attn, T);
    k_edge <<<(E * 32 + 255) / 256, 256>>>(xij, ft, E);
}